// round 2
// baseline (speedup 1.0000x reference)
#include <cuda_runtime.h>
#include <cstdint>
#include <math.h>

// Problem constants
#define BB    8
#define SS    2048
#define DIN   256
#define DIMN  256
#define GAMMA 0.9865

// GEMM tiling
#define BK  16
#define SST 72   // smem row stride (conflict-free fragment loads: 72 % 32 == 8)

// ---------------------------------------------------------------------------
// Scratch (device globals; no cudaMalloc allowed)
// ---------------------------------------------------------------------------
__device__ float g_Q[BB * SS * DIMN];                 // 16 MB
__device__ float g_K[BB * SS * DIMN];                 // 16 MB
__device__ float g_V[BB * SS * DIMN];                 // 16 MB (rescaled in place)
__device__ float g_scores[33554432];                  // BB*SS*SS = 128 MB
__device__ float g_part[BB * SS * (SS / 64)];         // per-row per-coltile partial sums

// ---------------------------------------------------------------------------
// tf32 split helpers + mma.sync wrapper
// ---------------------------------------------------------------------------
__device__ __forceinline__ void split_store(float x, float* Sh, float* Sl, int idx) {
    uint32_t u;
    asm("cvt.rna.tf32.f32 %0, %1;" : "=r"(u) : "f"(x));
    float h = __uint_as_float(u);
    Sh[idx] = h;
    Sl[idx] = x - h;   // exact residual of tf32 rounding
}

__device__ __forceinline__ void mma_tf32(float* c,
                                         uint32_t a0, uint32_t a1, uint32_t a2, uint32_t a3,
                                         uint32_t b0, uint32_t b1) {
    asm volatile(
        "mma.sync.aligned.m16n8k8.row.col.f32.tf32.tf32.f32 "
        "{%0,%1,%2,%3},{%4,%5,%6,%7},{%8,%9},{%0,%1,%2,%3};\n"
        : "+f"(c[0]), "+f"(c[1]), "+f"(c[2]), "+f"(c[3])
        : "r"(a0), "r"(a1), "r"(a2), "r"(a3), "r"(b0), "r"(b1));
}

// ---------------------------------------------------------------------------
// Tile loaders: gmem -> smem, splitting each value into (hi, lo) tf32 parts.
//   load_tileT: gmem tile is [64 rows x 16 k-cols], stored transposed S[k][row]
//   load_tileD: gmem tile is [16 k-rows x 64 cols], stored direct    S[k][col]
// 128 threads, 2 x float4 each.
// ---------------------------------------------------------------------------
__device__ __forceinline__ void load_tileT(const float* __restrict__ g, int ld,
                                           int row0, int k0,
                                           float* Sh, float* Sl, int tid) {
#pragma unroll
    for (int jj = 0; jj < 2; ++jj) {
        int q  = tid * 2 + jj;
        int r  = q >> 2;          // 0..63
        int cB = (q & 3) * 4;     // 0,4,8,12
        float4 v = *reinterpret_cast<const float4*>(g + (size_t)(row0 + r) * ld + (k0 + cB));
        split_store(v.x, Sh, Sl, (cB + 0) * SST + r);
        split_store(v.y, Sh, Sl, (cB + 1) * SST + r);
        split_store(v.z, Sh, Sl, (cB + 2) * SST + r);
        split_store(v.w, Sh, Sl, (cB + 3) * SST + r);
    }
}

__device__ __forceinline__ void load_tileD(const float* __restrict__ g, int ld,
                                           int k0, int col0,
                                           float* Sh, float* Sl, int tid) {
#pragma unroll
    for (int jj = 0; jj < 2; ++jj) {
        int q  = tid * 2 + jj;
        int k  = q >> 4;          // 0..15
        int cB = (q & 15) * 4;    // 0..60
        float4 v = *reinterpret_cast<const float4*>(g + (size_t)(k0 + k) * ld + (col0 + cB));
        split_store(v.x, Sh, Sl, k * SST + cB + 0);
        split_store(v.y, Sh, Sl, k * SST + cB + 1);
        split_store(v.z, Sh, Sl, k * SST + cB + 2);
        split_store(v.w, Sh, Sl, k * SST + cB + 3);
    }
}

// ---------------------------------------------------------------------------
// Core: one BK=16 chunk of a 64x64 block tile, warp computes 32x32.
// 3xTF32: acc += Ah*Bh + Al*Bh + Ah*Bl   (Al*Bl dropped: ~eps^2)
// ---------------------------------------------------------------------------
__device__ __forceinline__ void compute_k16(const float* __restrict__ Ah, const float* __restrict__ Al,
                                            const float* __restrict__ Bh, const float* __restrict__ Bl,
                                            int mBase, int nBase, int lane, float c[2][4][4]) {
#pragma unroll
    for (int ks = 0; ks < 2; ++ks) {
        const int kq = ks * 8 + (lane & 3);
        uint32_t ah[2][4], al[2][4];
#pragma unroll
        for (int mt = 0; mt < 2; ++mt) {
            const int r = mBase + mt * 16 + (lane >> 2);
            ah[mt][0] = __float_as_uint(Ah[kq * SST + r]);
            ah[mt][1] = __float_as_uint(Ah[kq * SST + r + 8]);
            ah[mt][2] = __float_as_uint(Ah[(kq + 4) * SST + r]);
            ah[mt][3] = __float_as_uint(Ah[(kq + 4) * SST + r + 8]);
            al[mt][0] = __float_as_uint(Al[kq * SST + r]);
            al[mt][1] = __float_as_uint(Al[kq * SST + r + 8]);
            al[mt][2] = __float_as_uint(Al[(kq + 4) * SST + r]);
            al[mt][3] = __float_as_uint(Al[(kq + 4) * SST + r + 8]);
        }
#pragma unroll
        for (int nt = 0; nt < 4; ++nt) {
            const int cc = nBase + nt * 8 + (lane >> 2);
            uint32_t bh0 = __float_as_uint(Bh[kq * SST + cc]);
            uint32_t bh1 = __float_as_uint(Bh[(kq + 4) * SST + cc]);
            uint32_t bl0 = __float_as_uint(Bl[kq * SST + cc]);
            uint32_t bl1 = __float_as_uint(Bl[(kq + 4) * SST + cc]);
#pragma unroll
            for (int mt = 0; mt < 2; ++mt) {
                mma_tf32(c[mt][nt], ah[mt][0], ah[mt][1], ah[mt][2], ah[mt][3], bh0, bh1);
                mma_tf32(c[mt][nt], al[mt][0], al[mt][1], al[mt][2], al[mt][3], bh0, bh1);
                mma_tf32(c[mt][nt], ah[mt][0], ah[mt][1], ah[mt][2], ah[mt][3], bl0, bl1);
            }
        }
    }
}

// ---------------------------------------------------------------------------
// Kernel 1: projections Q = xq@Wq, K = xk@Wk, V = xv@Wv
// grid (M/64=256, N/64=4, 3), block 128
// ---------------------------------------------------------------------------
__global__ void proj_kernel(const float* __restrict__ xq, const float* __restrict__ xk,
                            const float* __restrict__ xv,
                            const float* __restrict__ Wq, const float* __restrict__ Wk,
                            const float* __restrict__ Wv) {
    __shared__ float Ah[BK * SST], Al[BK * SST], Bh[BK * SST], Bl[BK * SST];
    const int tid = threadIdx.x, lane = tid & 31, warp = tid >> 5;
    const int mBase = (warp >> 1) * 32, nBase = (warp & 1) * 32;
    const int row0 = blockIdx.x * 64, col0 = blockIdx.y * 64;

    const float* X; const float* W; float* O;
    if (blockIdx.z == 0)      { X = xq; W = Wq; O = g_Q; }
    else if (blockIdx.z == 1) { X = xk; W = Wk; O = g_K; }
    else                      { X = xv; W = Wv; O = g_V; }

    float c[2][4][4];
#pragma unroll
    for (int a = 0; a < 2; ++a)
#pragma unroll
        for (int b = 0; b < 4; ++b)
#pragma unroll
            for (int d = 0; d < 4; ++d) c[a][b][d] = 0.f;

    for (int k0 = 0; k0 < DIN; k0 += BK) {
        load_tileT(X, DIN, row0, k0, Ah, Al, tid);
        load_tileD(W, DIMN, k0, col0, Bh, Bl, tid);
        __syncthreads();
        compute_k16(Ah, Al, Bh, Bl, mBase, nBase, lane, c);
        __syncthreads();
    }

#pragma unroll
    for (int mt = 0; mt < 2; ++mt)
#pragma unroll
        for (int nt = 0; nt < 4; ++nt) {
            int r  = row0 + mBase + mt * 16 + (lane >> 2);
            int cc = col0 + nBase + nt * 8 + (lane & 3) * 2;
            *reinterpret_cast<float2*>(O + (size_t)r * DIMN + cc) =
                make_float2(c[mt][nt][0], c[mt][nt][1]);
            *reinterpret_cast<float2*>(O + (size_t)(r + 8) * DIMN + cc) =
                make_float2(c[mt][nt][2], c[mt][nt][3]);
        }
}

// ---------------------------------------------------------------------------
// Kernel 2: scores = (Q K^T / sqrt(d)) * Dn  (lower-triangular block tiles only)
// Dn[i,j] = gamma^(j-i) / sqrt(sum|D|)   (NOTE: j-i => grows with i-j!)
// Also emits deterministic per-(row, coltile) partial row sums.
// grid (528 lower tiles, 8 batches), block 128
// ---------------------------------------------------------------------------
__global__ void scores_kernel(float scoreScale, float log2gi /* = log2(1/gamma) > 0 */) {
    __shared__ float Ah[BK * SST], Al[BK * SST], Bh[BK * SST], Bl[BK * SST];
    __shared__ float rowAcc[64];

    const int tid = threadIdx.x, lane = tid & 31, warp = tid >> 5;
    const int mBase = (warp >> 1) * 32, nBase = (warp & 1) * 32;
    const int L = blockIdx.x, b = blockIdx.y;

    int i = (int)((sqrtf(8.f * (float)L + 1.f) - 1.f) * 0.5f);
    while ((i + 1) * (i + 2) / 2 <= L) ++i;
    while (i * (i + 1) / 2 > L) --i;
    const int j = L - i * (i + 1) / 2;   // j <= i

    const float* Qp = g_Q + (size_t)b * SS * DIMN;
    const float* Kp = g_K + (size_t)b * SS * DIMN;

    if (tid < 64) rowAcc[tid] = 0.f;

    float c[2][4][4];
#pragma unroll
    for (int a = 0; a < 2; ++a)
#pragma unroll
        for (int x = 0; x < 4; ++x)
#pragma unroll
            for (int d = 0; d < 4; ++d) c[a][x][d] = 0.f;

    for (int k0 = 0; k0 < DIMN; k0 += BK) {
        load_tileT(Qp, DIMN, i * 64, k0, Ah, Al, tid);
        load_tileT(Kp, DIMN, j * 64, k0, Bh, Bl, tid);   // K rows are the "n" dim
        __syncthreads();
        compute_k16(Ah, Al, Bh, Bl, mBase, nBase, lane, c);
        __syncthreads();
    }

    float* Sp = g_scores + (size_t)b * SS * SS;
#pragma unroll
    for (int mt = 0; mt < 2; ++mt)
#pragma unroll
        for (int h = 0; h < 2; ++h) {
            const int lr   = mBase + mt * 16 + h * 8 + (lane >> 2);
            const int grow = i * 64 + lr;
            float rsum = 0.f;
#pragma unroll
            for (int nt = 0; nt < 4; ++nt) {
                const int gcol = j * 64 + nBase + nt * 8 + (lane & 3) * 2;
                float v0 = c[mt][nt][h * 2 + 0];
                float v1 = c[mt][nt][h * 2 + 1];
                const int d0 = grow - gcol;          // i - j >= 0 in valid region
                const int d1 = d0 - 1;
                // D[i,j] = gamma^(j-i) = (1/gamma)^(i-j) = exp2(d * log2(1/gamma))
                v0 = (d0 >= 0) ? v0 * scoreScale * exp2f((float)d0 * log2gi) : 0.f;
                v1 = (d1 >= 0) ? v1 * scoreScale * exp2f((float)d1 * log2gi) : 0.f;
                *reinterpret_cast<float2*>(Sp + (size_t)grow * SS + gcol) = make_float2(v0, v1);
                rsum += v0 + v1;
            }
            rsum += __shfl_xor_sync(0xffffffffu, rsum, 1);
            rsum += __shfl_xor_sync(0xffffffffu, rsum, 2);
            if ((lane & 3) == 0) atomicAdd(&rowAcc[lr], rsum);  // exactly 2 adds/slot: commutative -> deterministic
        }
    __syncthreads();
    if (tid < 64)
        g_part[((size_t)b * SS + i * 64 + tid) * 32 + j] = rowAcc[tid];
}

// ---------------------------------------------------------------------------
// Kernel 3: V[t,:] /= max(|rowsum_t|, 1)  (sequential, deterministic reduction)
// grid B*S blocks, 256 threads
// ---------------------------------------------------------------------------
__global__ void vprime_kernel() {
    const int row = blockIdx.x;          // 0..B*S-1
    const int s   = row & (SS - 1);
    __shared__ float inv;
    if (threadIdx.x == 0) {
        float acc = 0.f;
        const int jm = s >> 6;
        const float* p = g_part + (size_t)row * 32;
        for (int jt = 0; jt <= jm; ++jt) acc += p[jt];
        inv = 1.f / fmaxf(fabsf(acc), 1.f);
    }
    __syncthreads();
    g_V[(size_t)row * DIMN + threadIdx.x] *= inv;
}

// ---------------------------------------------------------------------------
// Kernel 4: out = scores @ V'   (triangular K loop: K = (i+1)*64)
// grid (32 mtiles, 4 ntiles, 8 batches), block 128
// ---------------------------------------------------------------------------
__global__ void out_kernel(float* __restrict__ out) {
    __shared__ float Ah[BK * SST], Al[BK * SST], Bh[BK * SST], Bl[BK * SST];
    const int tid = threadIdx.x, lane = tid & 31, warp = tid >> 5;
    const int mBase = (warp >> 1) * 32, nBase = (warp & 1) * 32;
    const int i = blockIdx.x;
    const int col0 = blockIdx.y * 64;
    const int b = blockIdx.z;

    const float* Sp = g_scores + (size_t)b * SS * SS;
    const float* Vp = g_V + (size_t)b * SS * DIMN;
    const int KK = (i + 1) * 64;

    float c[2][4][4];
#pragma unroll
    for (int a = 0; a < 2; ++a)
#pragma unroll
        for (int x = 0; x < 4; ++x)
#pragma unroll
            for (int d = 0; d < 4; ++d) c[a][x][d] = 0.f;

    for (int k0 = 0; k0 < KK; k0 += BK) {
        load_tileT(Sp, SS, i * 64, k0, Ah, Al, tid);
        load_tileD(Vp, DIMN, k0, col0, Bh, Bl, tid);
        __syncthreads();
        compute_k16(Ah, Al, Bh, Bl, mBase, nBase, lane, c);
        __syncthreads();
    }

    float* Ob = out + (size_t)b * SS * DIMN;
#pragma unroll
    for (int mt = 0; mt < 2; ++mt)
#pragma unroll
        for (int nt = 0; nt < 4; ++nt) {
            int r  = i * 64 + mBase + mt * 16 + (lane >> 2);
            int cc = col0 + nBase + nt * 8 + (lane & 3) * 2;
            *reinterpret_cast<float2*>(Ob + (size_t)r * DIMN + cc) =
                make_float2(c[mt][nt][0], c[mt][nt][1]);
            *reinterpret_cast<float2*>(Ob + (size_t)(r + 8) * DIMN + cc) =
                make_float2(c[mt][nt][2], c[mt][nt][3]);
        }
}

// ---------------------------------------------------------------------------
// Launch
// ---------------------------------------------------------------------------
extern "C" void kernel_launch(void* const* d_in, const int* in_sizes, int n_in,
                              void* d_out, int out_size) {
    const float* xq = (const float*)d_in[0];
    const float* xk = (const float*)d_in[1];
    const float* xv = (const float*)d_in[2];
    const float* Wq = (const float*)d_in[3];
    const float* Wk = (const float*)d_in[4];
    const float* Wv = (const float*)d_in[5];
    float* out = (float*)d_out;

    // sum|D| = sum_{d=0}^{S-1} (S-d) * gamma^(-d)   (D[i,j] = gamma^(j-i), i>=j)
    double acc = 0.0, gp = 1.0;
    const double ginv = 1.0 / GAMMA;
    for (int d = 0; d < SS; ++d) { acc += (double)(SS - d) * gp; gp *= ginv; }
    const float scoreScale = (float)(1.0 / (sqrt(acc) * 16.0));   // invNorm / sqrt(dim)
    const float log2gi = (float)(-log(GAMMA) / log(2.0));         // log2(1/gamma) > 0

    proj_kernel<<<dim3(256, 4, 3), 128>>>(xq, xk, xv, Wq, Wk, Wv);
    scores_kernel<<<dim3(528, 8), 128>>>(scoreScale, log2gi);
    vprime_kernel<<<BB * SS, 256>>>();
    out_kernel<<<dim3(32, 4, 8), 128>>>(out);
}

// round 3
// speedup vs baseline: 1.4207x; 1.4207x over previous
#include <cuda_runtime.h>
#include <cstdint>
#include <math.h>

// Problem constants
#define BB    8
#define SS    2048
#define DIN   256
#define DIMN  256
#define GAMMA 0.9865

// ---------------------------------------------------------------------------
// Scratch (device globals; no cudaMalloc allowed)
// ---------------------------------------------------------------------------
__device__ float g_Q[BB * SS * DIMN];                 // 16 MB
__device__ float g_K[BB * SS * DIMN];                 // 16 MB
__device__ float g_V[BB * SS * DIMN];                 // 16 MB (rescaled in place)
__device__ float g_scores[33554432];                  // BB*SS*SS = 128 MB
__device__ float g_part[BB * SS * 32];                // per-row per-coltile partial sums

__device__ __forceinline__ float4 ld4(const float* p) {
    return *reinterpret_cast<const float4*>(p);
}

// tf32 split at consume time: h = round-to-tf32(x), l = x - h (exact residual)
__device__ __forceinline__ void splitu(float x, uint32_t& h, uint32_t& l) {
    uint32_t u;
    asm("cvt.rna.tf32.f32 %0, %1;" : "=r"(u) : "f"(x));
    h = u;
    l = __float_as_uint(x - __uint_as_float(u));
}

__device__ __forceinline__ void mma_tf32(float* c,
                                         uint32_t a0, uint32_t a1, uint32_t a2, uint32_t a3,
                                         uint32_t b0, uint32_t b1) {
    asm volatile(
        "mma.sync.aligned.m16n8k8.row.col.f32.tf32.tf32.f32 "
        "{%0,%1,%2,%3},{%4,%5,%6,%7},{%8,%9},{%0,%1,%2,%3};\n"
        : "+f"(c[0]), "+f"(c[1]), "+f"(c[2]), "+f"(c[3])
        : "r"(a0), "r"(a1), "r"(a2), "r"(a3), "r"(b0), "r"(b1));
}

// ---------------------------------------------------------------------------
// Fragment-packed smem layouts (per 64x64x16 chunk):
//  A: float4 aSm[8][32]: slot (ks,mt4): [ (ks*4+mt4)*32 + ((r*4+kq)^((r>>1)&3)) ]
//     = ( A[k][row], A[k][row+8], A[k+4][row], A[k+4][row+8] ),
//       k = ks*8+kq, row = mt4*16+r.   Consumer: 1 LDS.128 per fragment.
//  B: float2 bSm[2][64][4]: [ (ks*64+cc)*4 + (kq ^ ((cc>>2)&3)) ]
//     = ( B[k][cc], B[k+4][cc] ).       Consumer: 1 LDS.64 per fragment.
// ---------------------------------------------------------------------------

// A loader: source row-major [m][k] (X, Q, scores). t in 0..63.
__device__ __forceinline__ void ldgA(const float* __restrict__ g, int ld, int row0, int k0,
                                     int t, float4 st[4]) {
    int rp = t & 31, ks = t >> 5, mt4 = rp >> 3, r = rp & 7;
    const float* p = g + (size_t)(row0 + mt4 * 16 + r) * ld + (k0 + ks * 8);
    st[0] = ld4(p); st[1] = ld4(p + 4);
    p += (size_t)8 * ld;
    st[2] = ld4(p); st[3] = ld4(p + 4);
}
__device__ __forceinline__ void stsA(float4* aSm, int t, const float4 st[4]) {
    int rp = t & 31, ks = t >> 5, mt4 = rp >> 3, r = rp & 7;
    int base = (ks * 4 + mt4) * 32, sw = (r >> 1) & 3, r4 = r * 4;
    aSm[base + ((r4 + 0) ^ sw)] = make_float4(st[0].x, st[2].x, st[1].x, st[3].x);
    aSm[base + ((r4 + 1) ^ sw)] = make_float4(st[0].y, st[2].y, st[1].y, st[3].y);
    aSm[base + ((r4 + 2) ^ sw)] = make_float4(st[0].z, st[2].z, st[1].z, st[3].z);
    aSm[base + ((r4 + 3) ^ sw)] = make_float4(st[0].w, st[2].w, st[1].w, st[3].w);
}

// B loader, direct source [k][n] (W, V). tb in 0..63, two tasks each.
__device__ __forceinline__ void ldgBD(const float* __restrict__ g, int ld, int k0, int col0,
                                      int tb, float4 st[4]) {
#pragma unroll
    for (int uu = 0; uu < 2; ++uu) {
        int u = tb + uu * 64, kq = u & 3, cg = (u >> 2) & 15, ks = u >> 6;
        const float* p = g + (size_t)(k0 + ks * 8 + kq) * ld + col0 + cg * 4;
        st[uu * 2 + 0] = ld4(p);
        st[uu * 2 + 1] = ld4(p + (size_t)4 * ld);
    }
}
__device__ __forceinline__ void stsBD(float2* bSm, int tb, const float4 st[4]) {
#pragma unroll
    for (int uu = 0; uu < 2; ++uu) {
        int u = tb + uu * 64, kq = u & 3, cg = (u >> 2) & 15, ks = u >> 6;
        int base = (ks * 64 + cg * 4) * 4 + (kq ^ (cg & 3));
        float4 lo = st[uu * 2 + 0], hi = st[uu * 2 + 1];
        bSm[base + 0]  = make_float2(lo.x, hi.x);
        bSm[base + 4]  = make_float2(lo.y, hi.y);
        bSm[base + 8]  = make_float2(lo.z, hi.z);
        bSm[base + 12] = make_float2(lo.w, hi.w);
    }
}

// B loader, transposed source [n][k] (K matrix). tb in 0..63, two tasks each.
__device__ __forceinline__ void ldgBT(const float* __restrict__ g, int ld, int row0, int k0,
                                      int tb, float4 st[4]) {
#pragma unroll
    for (int uu = 0; uu < 2; ++uu) {
        int u = tb + uu * 64, cc = u & 63, ks = u >> 6;
        const float* p = g + (size_t)(row0 + cc) * ld + k0 + ks * 8;
        st[uu * 2 + 0] = ld4(p);
        st[uu * 2 + 1] = ld4(p + 4);
    }
}
__device__ __forceinline__ void stsBT(float2* bSm, int tb, const float4 st[4]) {
#pragma unroll
    for (int uu = 0; uu < 2; ++uu) {
        int u = tb + uu * 64, cc = u & 63, ks = u >> 6;
        int sw = (cc >> 2) & 3;
        int base = (ks * 64 + cc) * 4;
        float4 lo = st[uu * 2 + 0], hi = st[uu * 2 + 1];
        bSm[base + (0 ^ sw)] = make_float2(lo.x, hi.x);
        bSm[base + (1 ^ sw)] = make_float2(lo.y, hi.y);
        bSm[base + (2 ^ sw)] = make_float2(lo.z, hi.z);
        bSm[base + (3 ^ sw)] = make_float2(lo.w, hi.w);
    }
}

// ---------------------------------------------------------------------------
// Compute one k16 chunk. Warp tile 32x32. 3xTF32 split (AhBh + AlBh + AhBl).
// ---------------------------------------------------------------------------
__device__ __forceinline__ void computeChunk(const float4* __restrict__ aSm,
                                             const float2* __restrict__ bSm,
                                             int mBase, int nBase, int lane,
                                             float acc[2][4][4]) {
    const int sl  = lane ^ ((lane >> 3) & 3);
    const int kqc = lane & 3;
    const int cr  = lane >> 2;
#pragma unroll
    for (int ks = 0; ks < 2; ++ks) {
        uint32_t ah[2][4], al[2][4];
#pragma unroll
        for (int mt = 0; mt < 2; ++mt) {
            float4 fa = aSm[(ks * 4 + (mBase >> 4) + mt) * 32 + sl];
            splitu(fa.x, ah[mt][0], al[mt][0]);
            splitu(fa.y, ah[mt][1], al[mt][1]);
            splitu(fa.z, ah[mt][2], al[mt][2]);
            splitu(fa.w, ah[mt][3], al[mt][3]);
        }
#pragma unroll
        for (int nt = 0; nt < 4; ++nt) {
            int cc = nBase + nt * 8 + cr;
            float2 fb = bSm[(ks * 64 + cc) * 4 + (kqc ^ ((cc >> 2) & 3))];
            uint32_t bh0, bl0, bh1, bl1;
            splitu(fb.x, bh0, bl0);
            splitu(fb.y, bh1, bl1);
#pragma unroll
            for (int mt = 0; mt < 2; ++mt) {
                mma_tf32(acc[mt][nt], ah[mt][0], ah[mt][1], ah[mt][2], ah[mt][3], bh0, bh1);
                mma_tf32(acc[mt][nt], al[mt][0], al[mt][1], al[mt][2], al[mt][3], bh0, bh1);
                mma_tf32(acc[mt][nt], ah[mt][0], ah[mt][1], ah[mt][2], ah[mt][3], bl0, bl1);
            }
        }
    }
}

// ---------------------------------------------------------------------------
// Double-buffered mainloop. BT selects B source layout (true = [n][k]).
// aSm has 2x256 float4, bSm 2x512 float2.
// ---------------------------------------------------------------------------
template <bool BT>
__device__ __forceinline__ void gemm_mainloop(
    const float* __restrict__ Ag, int lda, int arow0,
    const float* __restrict__ Bg, int ldb, int b0,
    int nChunks, int tid, int mBase, int nBase, int lane,
    float4* aSm, float2* bSm, float acc[2][4][4])
{
    float4 st[4];
    const bool isA = tid < 64;
    const int tb = tid & 63;
    if (isA)      ldgA(Ag, lda, arow0, 0, tb, st);
    else if (BT)  ldgBT(Bg, ldb, b0, 0, tb, st);
    else          ldgBD(Bg, ldb, 0, b0, tb, st);
    if (isA)      stsA(aSm, tb, st);
    else if (BT)  stsBT(bSm, tb, st);
    else          stsBD(bSm, tb, st);

    for (int c = 0; c < nChunks; ++c) {
        __syncthreads();
        const bool more = (c + 1) < nChunks;
        if (more) {
            const int k0 = (c + 1) * 16;
            if (isA)      ldgA(Ag, lda, arow0, k0, tb, st);
            else if (BT)  ldgBT(Bg, ldb, b0, k0, tb, st);
            else          ldgBD(Bg, ldb, k0, b0, tb, st);
        }
        const int cb = c & 1;
        computeChunk(aSm + cb * 256, bSm + cb * 512, mBase, nBase, lane, acc);
        if (more) {
            const int nb = (c + 1) & 1;
            if (isA)      stsA(aSm + nb * 256, tb, st);
            else if (BT)  stsBT(bSm + nb * 512, tb, st);
            else          stsBD(bSm + nb * 512, tb, st);
        }
    }
}

#define DECL_SMEM() \
    __shared__ float4 aSm[512]; \
    __shared__ float2 bSm[1024]

// ---------------------------------------------------------------------------
// Kernel 1: projections Q = xq@Wq, K = xk@Wk, V = xv@Wv
// grid (256, 4, 3), block 128
// ---------------------------------------------------------------------------
__global__ __launch_bounds__(128)
void proj_kernel(const float* __restrict__ xq, const float* __restrict__ xk,
                 const float* __restrict__ xv,
                 const float* __restrict__ Wq, const float* __restrict__ Wk,
                 const float* __restrict__ Wv) {
    DECL_SMEM();
    const int tid = threadIdx.x, lane = tid & 31, warp = tid >> 5;
    const int mBase = (warp >> 1) * 32, nBase = (warp & 1) * 32;
    const int row0 = blockIdx.x * 64, col0 = blockIdx.y * 64;

    const float* X; const float* W; float* O;
    if (blockIdx.z == 0)      { X = xq; W = Wq; O = g_Q; }
    else if (blockIdx.z == 1) { X = xk; W = Wk; O = g_K; }
    else                      { X = xv; W = Wv; O = g_V; }

    float acc[2][4][4];
#pragma unroll
    for (int a = 0; a < 2; ++a)
#pragma unroll
        for (int b = 0; b < 4; ++b)
#pragma unroll
            for (int d = 0; d < 4; ++d) acc[a][b][d] = 0.f;

    gemm_mainloop<false>(X, DIN, row0, W, DIMN, col0, DIN / 16,
                         tid, mBase, nBase, lane, aSm, bSm, acc);

#pragma unroll
    for (int mt = 0; mt < 2; ++mt)
#pragma unroll
        for (int nt = 0; nt < 4; ++nt) {
            int r  = row0 + mBase + mt * 16 + (lane >> 2);
            int cc = col0 + nBase + nt * 8 + (lane & 3) * 2;
            *reinterpret_cast<float2*>(O + (size_t)r * DIMN + cc) =
                make_float2(acc[mt][nt][0], acc[mt][nt][1]);
            *reinterpret_cast<float2*>(O + (size_t)(r + 8) * DIMN + cc) =
                make_float2(acc[mt][nt][2], acc[mt][nt][3]);
        }
}

// ---------------------------------------------------------------------------
// Kernel 2: scores = (Q K^T / sqrt(d)) * Dn, lower-triangular tiles.
// Dn[i,j] = gamma^(j-i) / sqrt(sum|D|)  (amplifying with i-j).
// grid (528, 8), block 128
// ---------------------------------------------------------------------------
__global__ __launch_bounds__(128)
void scores_kernel(float scoreScale, float log2gi) {
    DECL_SMEM();
    __shared__ float rowAcc[64];

    const int tid = threadIdx.x, lane = tid & 31, warp = tid >> 5;
    const int mBase = (warp >> 1) * 32, nBase = (warp & 1) * 32;
    const int L = blockIdx.x, b = blockIdx.y;

    int i = (int)((sqrtf(8.f * (float)L + 1.f) - 1.f) * 0.5f);
    while ((i + 1) * (i + 2) / 2 <= L) ++i;
    while (i * (i + 1) / 2 > L) --i;
    const int j = L - i * (i + 1) / 2;   // j <= i

    const float* Qp = g_Q + (size_t)b * SS * DIMN;
    const float* Kp = g_K + (size_t)b * SS * DIMN;

    if (tid < 64) rowAcc[tid] = 0.f;

    float acc[2][4][4];
#pragma unroll
    for (int a = 0; a < 2; ++a)
#pragma unroll
        for (int x = 0; x < 4; ++x)
#pragma unroll
            for (int d = 0; d < 4; ++d) acc[a][x][d] = 0.f;

    gemm_mainloop<true>(Qp, DIMN, i * 64, Kp, DIMN, j * 64, DIMN / 16,
                        tid, mBase, nBase, lane, aSm, bSm, acc);

    float* Sp = g_scores + (size_t)b * SS * SS;
#pragma unroll
    for (int mt = 0; mt < 2; ++mt)
#pragma unroll
        for (int h = 0; h < 2; ++h) {
            const int lr   = mBase + mt * 16 + h * 8 + (lane >> 2);
            const int grow = i * 64 + lr;
            float rsum = 0.f;
#pragma unroll
            for (int nt = 0; nt < 4; ++nt) {
                const int gcol = j * 64 + nBase + nt * 8 + (lane & 3) * 2;
                float v0 = acc[mt][nt][h * 2 + 0];
                float v1 = acc[mt][nt][h * 2 + 1];
                const int d0 = grow - gcol;
                const int d1 = d0 - 1;
                v0 = (d0 >= 0) ? v0 * scoreScale * exp2f((float)d0 * log2gi) : 0.f;
                v1 = (d1 >= 0) ? v1 * scoreScale * exp2f((float)d1 * log2gi) : 0.f;
                *reinterpret_cast<float2*>(Sp + (size_t)grow * SS + gcol) = make_float2(v0, v1);
                rsum += v0 + v1;
            }
            rsum += __shfl_xor_sync(0xffffffffu, rsum, 1);
            rsum += __shfl_xor_sync(0xffffffffu, rsum, 2);
            if ((lane & 3) == 0) atomicAdd(&rowAcc[lr], rsum);  // 2 commutative adds/slot: deterministic
        }
    __syncthreads();
    if (tid < 64)
        g_part[((size_t)b * SS + i * 64 + tid) * 32 + j] = rowAcc[tid];
}

// ---------------------------------------------------------------------------
// Kernel 3: V[t,:] /= max(|rowsum_t|, 1)  (sequential, deterministic)
// ---------------------------------------------------------------------------
__global__ void vprime_kernel() {
    const int row = blockIdx.x;
    const int s   = row & (SS - 1);
    __shared__ float inv;
    if (threadIdx.x == 0) {
        float acc = 0.f;
        const int jm = s >> 6;
        const float* p = g_part + (size_t)row * 32;
        for (int jt = 0; jt <= jm; ++jt) acc += p[jt];
        inv = 1.f / fmaxf(fabsf(acc), 1.f);
    }
    __syncthreads();
    g_V[(size_t)row * DIMN + threadIdx.x] *= inv;
}

// ---------------------------------------------------------------------------
// Kernel 4: out = scores @ V'   (triangular K loop)
// grid (32, 4, 8), block 128
// ---------------------------------------------------------------------------
__global__ __launch_bounds__(128)
void out_kernel(float* __restrict__ out) {
    DECL_SMEM();
    const int tid = threadIdx.x, lane = tid & 31, warp = tid >> 5;
    const int mBase = (warp >> 1) * 32, nBase = (warp & 1) * 32;
    const int i = blockIdx.x;
    const int col0 = blockIdx.y * 64;
    const int b = blockIdx.z;

    const float* Sp = g_scores + (size_t)b * SS * SS;
    const float* Vp = g_V + (size_t)b * SS * DIMN;

    float acc[2][4][4];
#pragma unroll
    for (int a = 0; a < 2; ++a)
#pragma unroll
        for (int x = 0; x < 4; ++x)
#pragma unroll
            for (int d = 0; d < 4; ++d) acc[a][x][d] = 0.f;

    gemm_mainloop<false>(Sp, SS, i * 64, Vp, DIMN, col0, (i + 1) * 4,
                         tid, mBase, nBase, lane, aSm, bSm, acc);

    float* Ob = out + (size_t)b * SS * DIMN;
#pragma unroll
    for (int mt = 0; mt < 2; ++mt)
#pragma unroll
        for (int nt = 0; nt < 4; ++nt) {
            int r  = i * 64 + mBase + mt * 16 + (lane >> 2);
            int cc = col0 + nBase + nt * 8 + (lane & 3) * 2;
            *reinterpret_cast<float2*>(Ob + (size_t)r * DIMN + cc) =
                make_float2(acc[mt][nt][0], acc[mt][nt][1]);
            *reinterpret_cast<float2*>(Ob + (size_t)(r + 8) * DIMN + cc) =
                make_float2(acc[mt][nt][2], acc[mt][nt][3]);
        }
}

// ---------------------------------------------------------------------------
// Launch
// ---------------------------------------------------------------------------
extern "C" void kernel_launch(void* const* d_in, const int* in_sizes, int n_in,
                              void* d_out, int out_size) {
    const float* xq = (const float*)d_in[0];
    const float* xk = (const float*)d_in[1];
    const float* xv = (const float*)d_in[2];
    const float* Wq = (const float*)d_in[3];
    const float* Wk = (const float*)d_in[4];
    const float* Wv = (const float*)d_in[5];
    float* out = (float*)d_out;

    // sum|D| = sum_{d=0}^{S-1} (S-d) * gamma^(-d)
    double acc = 0.0, gp = 1.0;
    const double ginv = 1.0 / GAMMA;
    for (int d = 0; d < SS; ++d) { acc += (double)(SS - d) * gp; gp *= ginv; }
    const float scoreScale = (float)(1.0 / (sqrt(acc) * 16.0));   // invNorm / sqrt(dim)
    const float log2gi = (float)(-log(GAMMA) / log(2.0));         // log2(1/gamma) > 0

    proj_kernel<<<dim3(256, 4, 3), 128>>>(xq, xk, xv, Wq, Wk, Wv);
    scores_kernel<<<dim3(528, 8), 128>>>(scoreScale, log2gi);
    vprime_kernel<<<BB * SS, 256>>>();
    out_kernel<<<dim3(32, 4, 8), 128>>>(out);
}

// round 5
// speedup vs baseline: 1.7012x; 1.1975x over previous
#include <cuda_runtime.h>
#include <cstdint>
#include <math.h>

// Problem constants
#define BB    8
#define SS    2048
#define DIN   256
#define DIMN  256
#define GAMMA 0.9865

// Block tile: 128 (M) x 64 (N), 128 threads, 4 warps, warp tile 64x32.
// ---------------------------------------------------------------------------
__device__ float g_Q[BB * SS * DIMN];
__device__ float g_K[BB * SS * DIMN];
__device__ float g_V[BB * SS * DIMN];
__device__ float g_scores[33554432];                  // BB*SS*SS = 128 MB
__device__ float g_part[BB * SS * 32];

__device__ __forceinline__ float4 ld4(const float* p) {
    return *reinterpret_cast<const float4*>(p);
}

// tf32 split: h = rna-tf32(x), l = x - h (exact residual)
__device__ __forceinline__ void splitu(float x, uint32_t& h, uint32_t& l) {
    uint32_t u;
    asm("cvt.rna.tf32.f32 %0, %1;" : "=r"(u) : "f"(x));
    h = u;
    l = __float_as_uint(x - __uint_as_float(u));
}
__device__ __forceinline__ uint32_t to_tf32(float x) {
    uint32_t u;
    asm("cvt.rna.tf32.f32 %0, %1;" : "=r"(u) : "f"(x));
    return u;
}

__device__ __forceinline__ void mma_tf32(float* c,
                                         uint32_t a0, uint32_t a1, uint32_t a2, uint32_t a3,
                                         uint32_t b0, uint32_t b1) {
    asm volatile(
        "mma.sync.aligned.m16n8k8.row.col.f32.tf32.tf32.f32 "
        "{%0,%1,%2,%3},{%4,%5,%6,%7},{%8,%9},{%0,%1,%2,%3};\n"
        : "+f"(c[0]), "+f"(c[1]), "+f"(c[2]), "+f"(c[3])
        : "r"(a0), "r"(a1), "r"(a2), "r"(a3), "r"(b0), "r"(b1));
}

// ---------------------------------------------------------------------------
// Smem fragment layouts per 128x64x16 chunk:
//  A: float4 aSm[16][32]: group g = ks*8+mg (mg = row/16), slot (rr*4+kq)^((rr>>1)&3)
//     = ( A[k][r], A[k][r+8], A[k+4][r], A[k+4][r+8] ), k=ks*8+kq, r=mg*16+rr.
//  B: float2 bSm[2][64][4]: [(ks*64+cc)*4 + (kq ^ ((cc>>2)&3))] = ( B[k][cc], B[k+4][cc] ).
// ---------------------------------------------------------------------------

// A: source row-major [m][k]. Thread t (0..127): ks=t>>6, mg=(t>>3)&7, r=t&7.
__device__ __forceinline__ void ldgA(const float* __restrict__ g, int ld, int row0, int k0,
                                     int t, float4 st[4]) {
    int ks = t >> 6, mg = (t >> 3) & 7, r = t & 7;
    const float* p = g + (size_t)(row0 + mg * 16 + r) * ld + (k0 + ks * 8);
    st[0] = ld4(p); st[1] = ld4(p + 4);
    p += (size_t)8 * ld;
    st[2] = ld4(p); st[3] = ld4(p + 4);
}
__device__ __forceinline__ void stsA(float4* aSm, int t, const float4 st[4]) {
    int ks = t >> 6, mg = (t >> 3) & 7, r = t & 7;
    int base = (ks * 8 + mg) * 32, sw = (r >> 1) & 3, r4 = r * 4;
    aSm[base + ((r4 + 0) ^ sw)] = make_float4(st[0].x, st[2].x, st[1].x, st[3].x);
    aSm[base + ((r4 + 1) ^ sw)] = make_float4(st[0].y, st[2].y, st[1].y, st[3].y);
    aSm[base + ((r4 + 2) ^ sw)] = make_float4(st[0].z, st[2].z, st[1].z, st[3].z);
    aSm[base + ((r4 + 3) ^ sw)] = make_float4(st[0].w, st[2].w, st[1].w, st[3].w);
}

// B direct [k][n] (W, V). Thread t: kq=t&3, cg=(t>>2)&15, ks=t>>6.
__device__ __forceinline__ void ldgBD(const float* __restrict__ g, int ld, int k0, int col0,
                                      int t, float4 st[2]) {
    int kq = t & 3, cg = (t >> 2) & 15, ks = t >> 6;
    const float* p = g + (size_t)(k0 + ks * 8 + kq) * ld + col0 + cg * 4;
    st[0] = ld4(p);
    st[1] = ld4(p + (size_t)4 * ld);
}
__device__ __forceinline__ void stsBD(float2* bSm, int t, const float4 st[2]) {
    int kq = t & 3, cg = (t >> 2) & 15, ks = t >> 6;
    int base = (ks * 64 + cg * 4) * 4 + (kq ^ (cg & 3));
    bSm[base + 0]  = make_float2(st[0].x, st[1].x);
    bSm[base + 4]  = make_float2(st[0].y, st[1].y);
    bSm[base + 8]  = make_float2(st[0].z, st[1].z);
    bSm[base + 12] = make_float2(st[0].w, st[1].w);
}

// B transposed [n][k] (K matrix). Thread t: cc=t&63, ks=t>>6.
__device__ __forceinline__ void ldgBT(const float* __restrict__ g, int ld, int row0, int k0,
                                      int t, float4 st[2]) {
    int cc = t & 63, ks = t >> 6;
    const float* p = g + (size_t)(row0 + cc) * ld + k0 + ks * 8;
    st[0] = ld4(p);
    st[1] = ld4(p + 4);
}
__device__ __forceinline__ void stsBT(float2* bSm, int t, const float4 st[2]) {
    int cc = t & 63, ks = t >> 6;
    int sw = (cc >> 2) & 3;
    int base = (ks * 64 + cc) * 4;
    bSm[base + (0 ^ sw)] = make_float2(st[0].x, st[1].x);
    bSm[base + (1 ^ sw)] = make_float2(st[0].y, st[1].y);
    bSm[base + (2 ^ sw)] = make_float2(st[0].z, st[1].z);
    bSm[base + (3 ^ sw)] = make_float2(st[0].w, st[1].w);
}

// ---------------------------------------------------------------------------
// Compute one k16 chunk. Warp tile 64x32. 2xTF32 split: acc += Ah*Bh + Al*Bh.
// ---------------------------------------------------------------------------
__device__ __forceinline__ void computeChunk(const float4* __restrict__ aSm,
                                             const float2* __restrict__ bSm,
                                             int mBase, int nBase, int lane,
                                             float acc[4][4][4]) {
    const int sl  = lane ^ ((lane >> 3) & 3);
    const int kqc = lane & 3;
    const int cr  = lane >> 2;
    const int mg0 = mBase >> 4;
#pragma unroll
    for (int ks = 0; ks < 2; ++ks) {
        uint32_t ah[4][4], al[4][4];
#pragma unroll
        for (int mt = 0; mt < 4; ++mt) {
            float4 fa = aSm[(ks * 8 + mg0 + mt) * 32 + sl];
            splitu(fa.x, ah[mt][0], al[mt][0]);
            splitu(fa.y, ah[mt][1], al[mt][1]);
            splitu(fa.z, ah[mt][2], al[mt][2]);
            splitu(fa.w, ah[mt][3], al[mt][3]);
        }
#pragma unroll
        for (int nt = 0; nt < 4; ++nt) {
            int cc = nBase + nt * 8 + cr;
            float2 fb = bSm[(ks * 64 + cc) * 4 + (kqc ^ ((cc >> 2) & 3))];
            uint32_t bh0 = to_tf32(fb.x);
            uint32_t bh1 = to_tf32(fb.y);
#pragma unroll
            for (int mt = 0; mt < 4; ++mt) {
                mma_tf32(acc[mt][nt], ah[mt][0], ah[mt][1], ah[mt][2], ah[mt][3], bh0, bh1);
                mma_tf32(acc[mt][nt], al[mt][0], al[mt][1], al[mt][2], al[mt][3], bh0, bh1);
            }
        }
    }
}

// ---------------------------------------------------------------------------
// Double-buffered mainloop. BT: B source is [n][k].
// aSm: 2 x 512 float4 (16 KB). bSm: 2 x 512 float2 (8 KB).
// ---------------------------------------------------------------------------
template <bool BT>
__device__ __forceinline__ void gemm_mainloop(
    const float* __restrict__ Ag, int lda, int arow0,
    const float* __restrict__ Bg, int ldb, int b0,
    int nChunks, int tid, int mBase, int nBase, int lane,
    float4* aSm, float2* bSm, float acc[4][4][4])
{
    float4 stA[4], stB[2];
    ldgA(Ag, lda, arow0, 0, tid, stA);
    if (BT) ldgBT(Bg, ldb, b0, 0, tid, stB);
    else    ldgBD(Bg, ldb, 0, b0, tid, stB);
    stsA(aSm, tid, stA);
    if (BT) stsBT(bSm, tid, stB);
    else    stsBD(bSm, tid, stB);

    for (int c = 0; c < nChunks; ++c) {
        __syncthreads();
        const bool more = (c + 1) < nChunks;
        if (more) {
            const int k0 = (c + 1) * 16;
            ldgA(Ag, lda, arow0, k0, tid, stA);
            if (BT) ldgBT(Bg, ldb, b0, k0, tid, stB);
            else    ldgBD(Bg, ldb, k0, b0, tid, stB);
        }
        const int cb = c & 1;
        computeChunk(aSm + cb * 512, bSm + cb * 512, mBase, nBase, lane, acc);
        if (more) {
            const int nb = (c + 1) & 1;
            stsA(aSm + nb * 512, tid, stA);
            if (BT) stsBT(bSm + nb * 512, tid, stB);
            else    stsBD(bSm + nb * 512, tid, stB);
        }
    }
}

#define DECL_SMEM() \
    __shared__ float4 aSm[1024]; \
    __shared__ float2 bSm[1024]

#define INIT_ACC(acc) \
    _Pragma("unroll") for (int _a = 0; _a < 4; ++_a) \
    _Pragma("unroll") for (int _b = 0; _b < 4; ++_b) \
    _Pragma("unroll") for (int _d = 0; _d < 4; ++_d) acc[_a][_b][_d] = 0.f

// ---------------------------------------------------------------------------
// Kernel 1: projections. grid (128, 4, 3), block 128
// ---------------------------------------------------------------------------
__global__ __launch_bounds__(128)
void proj_kernel(const float* __restrict__ xq, const float* __restrict__ xk,
                 const float* __restrict__ xv,
                 const float* __restrict__ Wq, const float* __restrict__ Wk,
                 const float* __restrict__ Wv) {
    DECL_SMEM();
    const int tid = threadIdx.x, lane = tid & 31, warp = tid >> 5;
    const int mBase = (warp >> 1) * 64, nBase = (warp & 1) * 32;
    const int row0 = blockIdx.x * 128, col0 = blockIdx.y * 64;

    const float* X; const float* W; float* O;
    if (blockIdx.z == 0)      { X = xq; W = Wq; O = g_Q; }
    else if (blockIdx.z == 1) { X = xk; W = Wk; O = g_K; }
    else                      { X = xv; W = Wv; O = g_V; }

    float acc[4][4][4];
    INIT_ACC(acc);

    gemm_mainloop<false>(X, DIN, row0, W, DIMN, col0, DIN / 16,
                         tid, mBase, nBase, lane, aSm, bSm, acc);

#pragma unroll
    for (int mt = 0; mt < 4; ++mt)
#pragma unroll
        for (int nt = 0; nt < 4; ++nt) {
            int r  = row0 + mBase + mt * 16 + (lane >> 2);
            int cc = col0 + nBase + nt * 8 + (lane & 3) * 2;
            *reinterpret_cast<float2*>(O + (size_t)r * DIMN + cc) =
                make_float2(acc[mt][nt][0], acc[mt][nt][1]);
            *reinterpret_cast<float2*>(O + (size_t)(r + 8) * DIMN + cc) =
                make_float2(acc[mt][nt][2], acc[mt][nt][3]);
        }
}

// ---------------------------------------------------------------------------
// Kernel 2: scores = (Q K^T / sqrt(d)) * Dn, lower-triangular 128x64 tiles.
// grid (272, 8): L = i2*(i2+1) + j, j in 0..2*i2+1.
// ---------------------------------------------------------------------------
__global__ __launch_bounds__(128)
void scores_kernel(float scoreScale, float log2gi) {
    DECL_SMEM();
    __shared__ float rowAcc[128];

    const int tid = threadIdx.x, lane = tid & 31, warp = tid >> 5;
    const int mBase = (warp >> 1) * 64, nBase = (warp & 1) * 32;
    const int L = blockIdx.x, b = blockIdx.y;

    int i2 = (int)((sqrtf(4.f * (float)L + 1.f) - 1.f) * 0.5f);
    while ((i2 + 1) * (i2 + 2) <= L) ++i2;
    while (i2 * (i2 + 1) > L) --i2;
    const int j = L - i2 * (i2 + 1);     // 0 <= j <= 2*i2+1

    const float* Qp = g_Q + (size_t)b * SS * DIMN;
    const float* Kp = g_K + (size_t)b * SS * DIMN;

    rowAcc[tid] = 0.f;

    float acc[4][4][4];
    INIT_ACC(acc);

    gemm_mainloop<true>(Qp, DIMN, i2 * 128, Kp, DIMN, j * 64, DIMN / 16,
                        tid, mBase, nBase, lane, aSm, bSm, acc);

    float* Sp = g_scores + (size_t)b * SS * SS;
#pragma unroll
    for (int mt = 0; mt < 4; ++mt)
#pragma unroll
        for (int h = 0; h < 2; ++h) {
            const int lr   = mBase + mt * 16 + h * 8 + (lane >> 2);
            const int grow = i2 * 128 + lr;
            float rsum = 0.f;
#pragma unroll
            for (int nt = 0; nt < 4; ++nt) {
                const int gcol = j * 64 + nBase + nt * 8 + (lane & 3) * 2;
                float v0 = acc[mt][nt][h * 2 + 0];
                float v1 = acc[mt][nt][h * 2 + 1];
                const int d0 = grow - gcol;
                const int d1 = d0 - 1;
                // D[i,j] = gamma^(j-i) = exp2((i-j) * log2(1/gamma))
                v0 = (d0 >= 0) ? v0 * scoreScale * exp2f((float)d0 * log2gi) : 0.f;
                v1 = (d1 >= 0) ? v1 * scoreScale * exp2f((float)d1 * log2gi) : 0.f;
                *reinterpret_cast<float2*>(Sp + (size_t)grow * SS + gcol) = make_float2(v0, v1);
                rsum += v0 + v1;
            }
            rsum += __shfl_xor_sync(0xffffffffu, rsum, 1);
            rsum += __shfl_xor_sync(0xffffffffu, rsum, 2);
            if ((lane & 3) == 0) atomicAdd(&rowAcc[lr], rsum);  // 2 commutative adds/slot
        }
    __syncthreads();
    g_part[((size_t)b * SS + i2 * 128 + tid) * 32 + j] = rowAcc[tid];
}

// ---------------------------------------------------------------------------
// Kernel 3: V[t,:] /= max(|rowsum_t|, 1)  (sequential, deterministic)
// ---------------------------------------------------------------------------
__global__ void vprime_kernel() {
    const int row = blockIdx.x;
    const int s   = row & (SS - 1);
    __shared__ float inv;
    if (threadIdx.x == 0) {
        float acc = 0.f;
        const int jm = s >> 6;
        const float* p = g_part + (size_t)row * 32;
        for (int jt = 0; jt <= jm; ++jt) acc += p[jt];
        inv = 1.f / fmaxf(fabsf(acc), 1.f);
    }
    __syncthreads();
    g_V[(size_t)row * DIMN + threadIdx.x] *= inv;
}

// ---------------------------------------------------------------------------
// Kernel 4: out = scores @ V'. grid (16, 4, 8), big tiles first.
// ---------------------------------------------------------------------------
__global__ __launch_bounds__(128)
void out_kernel(float* __restrict__ out) {
    DECL_SMEM();
    const int tid = threadIdx.x, lane = tid & 31, warp = tid >> 5;
    const int mBase = (warp >> 1) * 64, nBase = (warp & 1) * 32;
    const int i2 = 15 - blockIdx.x;     // big K first for wave balance
    const int col0 = blockIdx.y * 64;
    const int b = blockIdx.z;

    const float* Sp = g_scores + (size_t)b * SS * SS;
    const float* Vp = g_V + (size_t)b * SS * DIMN;

    float acc[4][4][4];
    INIT_ACC(acc);

    gemm_mainloop<false>(Sp, SS, i2 * 128, Vp, DIMN, col0, (i2 + 1) * 8,
                         tid, mBase, nBase, lane, aSm, bSm, acc);

    float* Ob = out + (size_t)b * SS * DIMN;
#pragma unroll
    for (int mt = 0; mt < 4; ++mt)
#pragma unroll
        for (int nt = 0; nt < 4; ++nt) {
            int r  = i2 * 128 + mBase + mt * 16 + (lane >> 2);
            int cc = col0 + nBase + nt * 8 + (lane & 3) * 2;
            *reinterpret_cast<float2*>(Ob + (size_t)r * DIMN + cc) =
                make_float2(acc[mt][nt][0], acc[mt][nt][1]);
            *reinterpret_cast<float2*>(Ob + (size_t)(r + 8) * DIMN + cc) =
                make_float2(acc[mt][nt][2], acc[mt][nt][3]);
        }
}

// ---------------------------------------------------------------------------
// Launch
// ---------------------------------------------------------------------------
extern "C" void kernel_launch(void* const* d_in, const int* in_sizes, int n_in,
                              void* d_out, int out_size) {
    const float* xq = (const float*)d_in[0];
    const float* xk = (const float*)d_in[1];
    const float* xv = (const float*)d_in[2];
    const float* Wq = (const float*)d_in[3];
    const float* Wk = (const float*)d_in[4];
    const float* Wv = (const float*)d_in[5];
    float* out = (float*)d_out;

    // sum|D| = sum_{d=0}^{S-1} (S-d) * gamma^(-d)
    double acc = 0.0, gp = 1.0;
    const double ginv = 1.0 / GAMMA;
    for (int d = 0; d < SS; ++d) { acc += (double)(SS - d) * gp; gp *= ginv; }
    const float scoreScale = (float)(1.0 / (sqrt(acc) * 16.0));   // invNorm / sqrt(dim)
    const float log2gi = (float)(-log(GAMMA) / log(2.0));         // log2(1/gamma) > 0

    proj_kernel<<<dim3(128, 4, 3), 128>>>(xq, xk, xv, Wq, Wk, Wv);
    scores_kernel<<<dim3(272, 8), 128>>>(scoreScale, log2gi);
    vprime_kernel<<<BB * SS, 256>>>();
    out_kernel<<<dim3(16, 4, 8), 128>>>(out);
}

// round 6
// speedup vs baseline: 1.8737x; 1.1014x over previous
#include <cuda_runtime.h>
#include <cstdint>
#include <math.h>

// Problem constants
#define BB    8
#define SS    2048
#define DIN   256
#define DIMN  256
#define GAMMA 0.9865

// Block tile: 128 (M) x 64 (N), 128 threads, 4 warps, warp tile 64x32.
// ---------------------------------------------------------------------------
__device__ float g_Q[BB * SS * DIMN];
__device__ float g_K[BB * SS * DIMN];
__device__ float g_V[BB * SS * DIMN];
__device__ float g_scores[33554432];                  // BB*SS*SS = 128 MB
__device__ float g_part[BB * SS * 32];

__device__ __forceinline__ float4 ld4(const float* p) {
    return *reinterpret_cast<const float4*>(p);
}

// tf32 split: h = rna-tf32(x), l = x - h (exact residual)
__device__ __forceinline__ void splitu(float x, uint32_t& h, uint32_t& l) {
    uint32_t u;
    asm("cvt.rna.tf32.f32 %0, %1;" : "=r"(u) : "f"(x));
    h = u;
    l = __float_as_uint(x - __uint_as_float(u));
}
__device__ __forceinline__ uint32_t to_tf32(float x) {
    uint32_t u;
    asm("cvt.rna.tf32.f32 %0, %1;" : "=r"(u) : "f"(x));
    return u;
}

__device__ __forceinline__ void mma_tf32(float* c,
                                         uint32_t a0, uint32_t a1, uint32_t a2, uint32_t a3,
                                         uint32_t b0, uint32_t b1) {
    asm volatile(
        "mma.sync.aligned.m16n8k8.row.col.f32.tf32.tf32.f32 "
        "{%0,%1,%2,%3},{%4,%5,%6,%7},{%8,%9},{%0,%1,%2,%3};\n"
        : "+f"(c[0]), "+f"(c[1]), "+f"(c[2]), "+f"(c[3])
        : "r"(a0), "r"(a1), "r"(a2), "r"(a3), "r"(b0), "r"(b1));
}

// ---------------------------------------------------------------------------
// Smem fragment layouts per 128x64x16 chunk (same as R5):
//  A: float4 aSm[16][32], B: float2 bSm[2][64][4], XOR-swizzled.
// ---------------------------------------------------------------------------

__device__ __forceinline__ void ldgA(const float* __restrict__ g, int ld, int row0, int k0,
                                     int t, float4 st[4]) {
    int ks = t >> 6, mg = (t >> 3) & 7, r = t & 7;
    const float* p = g + (size_t)(row0 + mg * 16 + r) * ld + (k0 + ks * 8);
    st[0] = ld4(p); st[1] = ld4(p + 4);
    p += (size_t)8 * ld;
    st[2] = ld4(p); st[3] = ld4(p + 4);
}
__device__ __forceinline__ void stsA(float4* aSm, int t, const float4 st[4]) {
    int ks = t >> 6, mg = (t >> 3) & 7, r = t & 7;
    int base = (ks * 8 + mg) * 32, sw = (r >> 1) & 3, r4 = r * 4;
    aSm[base + ((r4 + 0) ^ sw)] = make_float4(st[0].x, st[2].x, st[1].x, st[3].x);
    aSm[base + ((r4 + 1) ^ sw)] = make_float4(st[0].y, st[2].y, st[1].y, st[3].y);
    aSm[base + ((r4 + 2) ^ sw)] = make_float4(st[0].z, st[2].z, st[1].z, st[3].z);
    aSm[base + ((r4 + 3) ^ sw)] = make_float4(st[0].w, st[2].w, st[1].w, st[3].w);
}

__device__ __forceinline__ void ldgBD(const float* __restrict__ g, int ld, int k0, int col0,
                                      int t, float4 st[2]) {
    int kq = t & 3, cg = (t >> 2) & 15, ks = t >> 6;
    const float* p = g + (size_t)(k0 + ks * 8 + kq) * ld + col0 + cg * 4;
    st[0] = ld4(p);
    st[1] = ld4(p + (size_t)4 * ld);
}
__device__ __forceinline__ void stsBD(float2* bSm, int t, const float4 st[2]) {
    int kq = t & 3, cg = (t >> 2) & 15, ks = t >> 6;
    int base = (ks * 64 + cg * 4) * 4 + (kq ^ (cg & 3));
    bSm[base + 0]  = make_float2(st[0].x, st[1].x);
    bSm[base + 4]  = make_float2(st[0].y, st[1].y);
    bSm[base + 8]  = make_float2(st[0].z, st[1].z);
    bSm[base + 12] = make_float2(st[0].w, st[1].w);
}

__device__ __forceinline__ void ldgBT(const float* __restrict__ g, int ld, int row0, int k0,
                                      int t, float4 st[2]) {
    int cc = t & 63, ks = t >> 6;
    const float* p = g + (size_t)(row0 + cc) * ld + k0 + ks * 8;
    st[0] = ld4(p);
    st[1] = ld4(p + 4);
}
__device__ __forceinline__ void stsBT(float2* bSm, int t, const float4 st[2]) {
    int cc = t & 63, ks = t >> 6;
    int sw = (cc >> 2) & 3;
    int base = (ks * 64 + cc) * 4;
    bSm[base + (0 ^ sw)] = make_float2(st[0].x, st[1].x);
    bSm[base + (1 ^ sw)] = make_float2(st[0].y, st[1].y);
    bSm[base + (2 ^ sw)] = make_float2(st[0].z, st[1].z);
    bSm[base + (3 ^ sw)] = make_float2(st[0].w, st[1].w);
}

// ---------------------------------------------------------------------------
// Compute one k16 chunk. Warp tile 64x32. 2xTF32 split: acc += Ah*Bh + Al*Bh.
// ---------------------------------------------------------------------------
__device__ __forceinline__ void computeChunk(const float4* __restrict__ aSm,
                                             const float2* __restrict__ bSm,
                                             int mBase, int nBase, int lane,
                                             float acc[4][4][4]) {
    const int sl  = lane ^ ((lane >> 3) & 3);
    const int kqc = lane & 3;
    const int cr  = lane >> 2;
    const int mg0 = mBase >> 4;
#pragma unroll
    for (int ks = 0; ks < 2; ++ks) {
        uint32_t ah[4][4], al[4][4];
#pragma unroll
        for (int mt = 0; mt < 4; ++mt) {
            float4 fa = aSm[(ks * 8 + mg0 + mt) * 32 + sl];
            splitu(fa.x, ah[mt][0], al[mt][0]);
            splitu(fa.y, ah[mt][1], al[mt][1]);
            splitu(fa.z, ah[mt][2], al[mt][2]);
            splitu(fa.w, ah[mt][3], al[mt][3]);
        }
#pragma unroll
        for (int nt = 0; nt < 4; ++nt) {
            int cc = nBase + nt * 8 + cr;
            float2 fb = bSm[(ks * 64 + cc) * 4 + (kqc ^ ((cc >> 2) & 3))];
            uint32_t bh0 = to_tf32(fb.x);
            uint32_t bh1 = to_tf32(fb.y);
#pragma unroll
            for (int mt = 0; mt < 4; ++mt) {
                mma_tf32(acc[mt][nt], ah[mt][0], ah[mt][1], ah[mt][2], ah[mt][3], bh0, bh1);
                mma_tf32(acc[mt][nt], al[mt][0], al[mt][1], al[mt][2], al[mt][3], bh0, bh1);
            }
        }
    }
}

// ---------------------------------------------------------------------------
// Double-buffered mainloop. BT: B source is [n][k].
// ---------------------------------------------------------------------------
template <bool BT>
__device__ __forceinline__ void gemm_mainloop(
    const float* __restrict__ Ag, int lda, int arow0,
    const float* __restrict__ Bg, int ldb, int b0,
    int nChunks, int tid, int mBase, int nBase, int lane,
    float4* aSm, float2* bSm, float acc[4][4][4])
{
    float4 stA[4], stB[2];
    ldgA(Ag, lda, arow0, 0, tid, stA);
    if (BT) ldgBT(Bg, ldb, b0, 0, tid, stB);
    else    ldgBD(Bg, ldb, 0, b0, tid, stB);
    stsA(aSm, tid, stA);
    if (BT) stsBT(bSm, tid, stB);
    else    stsBD(bSm, tid, stB);

    for (int c = 0; c < nChunks; ++c) {
        __syncthreads();
        const bool more = (c + 1) < nChunks;
        if (more) {
            const int k0 = (c + 1) * 16;
            ldgA(Ag, lda, arow0, k0, tid, stA);
            if (BT) ldgBT(Bg, ldb, b0, k0, tid, stB);
            else    ldgBD(Bg, ldb, k0, b0, tid, stB);
        }
        const int cb = c & 1;
        computeChunk(aSm + cb * 512, bSm + cb * 512, mBase, nBase, lane, acc);
        if (more) {
            const int nb = (c + 1) & 1;
            stsA(aSm + nb * 512, tid, stA);
            if (BT) stsBT(bSm + nb * 512, tid, stB);
            else    stsBD(bSm + nb * 512, tid, stB);
        }
    }
}

#define DECL_SMEM() \
    __shared__ float4 aSm[1024]; \
    __shared__ float2 bSm[1024]

#define INIT_ACC(acc) \
    _Pragma("unroll") for (int _a = 0; _a < 4; ++_a) \
    _Pragma("unroll") for (int _b = 0; _b < 4; ++_b) \
    _Pragma("unroll") for (int _d = 0; _d < 4; ++_d) acc[_a][_b][_d] = 0.f

// ---------------------------------------------------------------------------
// Kernel 1: projections. grid (128, 4, 3), block 128
// ---------------------------------------------------------------------------
__global__ __launch_bounds__(128, 3)
void proj_kernel(const float* __restrict__ xq, const float* __restrict__ xk,
                 const float* __restrict__ xv,
                 const float* __restrict__ Wq, const float* __restrict__ Wk,
                 const float* __restrict__ Wv) {
    DECL_SMEM();
    const int tid = threadIdx.x, lane = tid & 31, warp = tid >> 5;
    const int mBase = (warp >> 1) * 64, nBase = (warp & 1) * 32;
    const int row0 = blockIdx.x * 128, col0 = blockIdx.y * 64;

    const float* X; const float* W; float* O;
    if (blockIdx.z == 0)      { X = xq; W = Wq; O = g_Q; }
    else if (blockIdx.z == 1) { X = xk; W = Wk; O = g_K; }
    else                      { X = xv; W = Wv; O = g_V; }

    float acc[4][4][4];
    INIT_ACC(acc);

    gemm_mainloop<false>(X, DIN, row0, W, DIMN, col0, DIN / 16,
                         tid, mBase, nBase, lane, aSm, bSm, acc);

#pragma unroll
    for (int mt = 0; mt < 4; ++mt)
#pragma unroll
        for (int nt = 0; nt < 4; ++nt) {
            int r  = row0 + mBase + mt * 16 + (lane >> 2);
            int cc = col0 + nBase + nt * 8 + (lane & 3) * 2;
            *reinterpret_cast<float2*>(O + (size_t)r * DIMN + cc) =
                make_float2(acc[mt][nt][0], acc[mt][nt][1]);
            *reinterpret_cast<float2*>(O + (size_t)(r + 8) * DIMN + cc) =
                make_float2(acc[mt][nt][2], acc[mt][nt][3]);
        }
}

// ---------------------------------------------------------------------------
// Kernel 2: scores = (Q K^T / sqrt(d)) * Dn, lower-triangular 128x64 tiles.
// grid (272, 8): L = i2*(i2+1) + j, j in 0..2*i2+1.
// ---------------------------------------------------------------------------
__global__ __launch_bounds__(128, 3)
void scores_kernel(float scoreScale, float log2gi) {
    DECL_SMEM();
    __shared__ float rowAcc[128];

    const int tid = threadIdx.x, lane = tid & 31, warp = tid >> 5;
    const int mBase = (warp >> 1) * 64, nBase = (warp & 1) * 32;
    const int L = blockIdx.x, b = blockIdx.y;

    int i2 = (int)((sqrtf(4.f * (float)L + 1.f) - 1.f) * 0.5f);
    while ((i2 + 1) * (i2 + 2) <= L) ++i2;
    while (i2 * (i2 + 1) > L) --i2;
    const int j = L - i2 * (i2 + 1);     // 0 <= j <= 2*i2+1

    const float* Qp = g_Q + (size_t)b * SS * DIMN;
    const float* Kp = g_K + (size_t)b * SS * DIMN;

    rowAcc[tid] = 0.f;

    float acc[4][4][4];
    INIT_ACC(acc);

    gemm_mainloop<true>(Qp, DIMN, i2 * 128, Kp, DIMN, j * 64, DIMN / 16,
                        tid, mBase, nBase, lane, aSm, bSm, acc);

    float* Sp = g_scores + (size_t)b * SS * SS;
#pragma unroll
    for (int mt = 0; mt < 4; ++mt)
#pragma unroll
        for (int h = 0; h < 2; ++h) {
            const int lr   = mBase + mt * 16 + h * 8 + (lane >> 2);
            const int grow = i2 * 128 + lr;
            float rsum = 0.f;
#pragma unroll
            for (int nt = 0; nt < 4; ++nt) {
                const int gcol = j * 64 + nBase + nt * 8 + (lane & 3) * 2;
                float v0 = acc[mt][nt][h * 2 + 0];
                float v1 = acc[mt][nt][h * 2 + 1];
                const int d0 = grow - gcol;
                const int d1 = d0 - 1;
                // D[i,j] = gamma^(j-i) = exp2((i-j) * log2(1/gamma))
                v0 = (d0 >= 0) ? v0 * scoreScale * exp2f((float)d0 * log2gi) : 0.f;
                v1 = (d1 >= 0) ? v1 * scoreScale * exp2f((float)d1 * log2gi) : 0.f;
                *reinterpret_cast<float2*>(Sp + (size_t)grow * SS + gcol) = make_float2(v0, v1);
                rsum += v0 + v1;
            }
            rsum += __shfl_xor_sync(0xffffffffu, rsum, 1);
            rsum += __shfl_xor_sync(0xffffffffu, rsum, 2);
            if ((lane & 3) == 0) atomicAdd(&rowAcc[lr], rsum);  // 2 commutative adds/slot
        }
    __syncthreads();
    g_part[((size_t)b * SS + i2 * 128 + tid) * 32 + j] = rowAcc[tid];
}

// ---------------------------------------------------------------------------
// Kernel 3: V[t,:] /= max(|rowsum_t|, 1)  (sequential, deterministic)
// ---------------------------------------------------------------------------
__global__ void vprime_kernel() {
    const int row = blockIdx.x;
    const int s   = row & (SS - 1);
    __shared__ float inv;
    if (threadIdx.x == 0) {
        float acc = 0.f;
        const int jm = s >> 6;
        const float* p = g_part + (size_t)row * 32;
        for (int jt = 0; jt <= jm; ++jt) acc += p[jt];
        inv = 1.f / fmaxf(fabsf(acc), 1.f);
    }
    __syncthreads();
    g_V[(size_t)row * DIMN + threadIdx.x] *= inv;
}

// ---------------------------------------------------------------------------
// Kernel 4: out = scores @ V'. Uniform-work pairing: block x handles row
// tiles i2 = x and 15 - x => every block does exactly 17*8 chunks.
// grid (8, 4, 8) = 256 identical blocks -> single balanced wave.
// ---------------------------------------------------------------------------
__global__ __launch_bounds__(128, 3)
void out_kernel(float* __restrict__ out) {
    DECL_SMEM();
    const int tid = threadIdx.x, lane = tid & 31, warp = tid >> 5;
    const int mBase = (warp >> 1) * 64, nBase = (warp & 1) * 32;
    const int col0 = blockIdx.y * 64;
    const int b = blockIdx.z;

    const float* Sp = g_scores + (size_t)b * SS * SS;
    const float* Vp = g_V + (size_t)b * SS * DIMN;
    float* Ob = out + (size_t)b * SS * DIMN;

#pragma unroll 1
    for (int half = 0; half < 2; ++half) {
        const int i2 = half ? (15 - (int)blockIdx.x) : (int)blockIdx.x;

        __syncthreads();   // protect smem reuse across the two mainloops

        float acc[4][4][4];
        INIT_ACC(acc);

        gemm_mainloop<false>(Sp, SS, i2 * 128, Vp, DIMN, col0, (i2 + 1) * 8,
                             tid, mBase, nBase, lane, aSm, bSm, acc);

#pragma unroll
        for (int mt = 0; mt < 4; ++mt)
#pragma unroll
            for (int nt = 0; nt < 4; ++nt) {
                int r  = i2 * 128 + mBase + mt * 16 + (lane >> 2);
                int cc = col0 + nBase + nt * 8 + (lane & 3) * 2;
                *reinterpret_cast<float2*>(Ob + (size_t)r * DIMN + cc) =
                    make_float2(acc[mt][nt][0], acc[mt][nt][1]);
                *reinterpret_cast<float2*>(Ob + (size_t)(r + 8) * DIMN + cc) =
                    make_float2(acc[mt][nt][2], acc[mt][nt][3]);
            }
    }
}

// ---------------------------------------------------------------------------
// Launch
// ---------------------------------------------------------------------------
extern "C" void kernel_launch(void* const* d_in, const int* in_sizes, int n_in,
                              void* d_out, int out_size) {
    const float* xq = (const float*)d_in[0];
    const float* xk = (const float*)d_in[1];
    const float* xv = (const float*)d_in[2];
    const float* Wq = (const float*)d_in[3];
    const float* Wk = (const float*)d_in[4];
    const float* Wv = (const float*)d_in[5];
    float* out = (float*)d_out;

    // sum|D| = sum_{d=0}^{S-1} (S-d) * gamma^(-d)
    double acc = 0.0, gp = 1.0;
    const double ginv = 1.0 / GAMMA;
    for (int d = 0; d < SS; ++d) { acc += (double)(SS - d) * gp; gp *= ginv; }
    const float scoreScale = (float)(1.0 / (sqrt(acc) * 16.0));   // invNorm / sqrt(dim)
    const float log2gi = (float)(-log(GAMMA) / log(2.0));         // log2(1/gamma) > 0

    proj_kernel<<<dim3(128, 4, 3), 128>>>(xq, xk, xv, Wq, Wk, Wv);
    scores_kernel<<<dim3(272, 8), 128>>>(scoreScale, log2gi);
    vprime_kernel<<<BB * SS, 256>>>();
    out_kernel<<<dim3(8, 4, 8), 128>>>(out);
}

// round 9
// speedup vs baseline: 1.9240x; 1.0268x over previous
#include <cuda_runtime.h>
#include <cstdint>
#include <math.h>

// Problem constants
#define BB    8
#define SS    2048
#define DIN   256
#define DIMN  256
#define GAMMA 0.9865

// Block tile: 128 (M) x 64 (N), 128 threads, 4 warps, warp tile 64x32.
// Decay folded into projections: Qt_i = Q_i * g^-i * s, Kt_j = K_j * g^j * s,
// s = sqrt(scoreScale)  =>  scores = tril(Qt Kt^T), pure masked GEMM.
// ---------------------------------------------------------------------------
__device__ float g_Q[BB * SS * DIMN];
__device__ float g_K[BB * SS * DIMN];
__device__ float g_V[BB * SS * DIMN];
__device__ float g_scores[33554432];                  // BB*SS*SS = 128 MB
__device__ float g_part[BB * SS * 32];

__device__ __forceinline__ float4 ld4(const float* p) {
    return *reinterpret_cast<const float4*>(p);
}

// tf32 split: h = rna-tf32(x), l = x - h (exact residual)
__device__ __forceinline__ void splitu(float x, uint32_t& h, uint32_t& l) {
    uint32_t u;
    asm("cvt.rna.tf32.f32 %0, %1;" : "=r"(u) : "f"(x));
    h = u;
    l = __float_as_uint(x - __uint_as_float(u));
}
__device__ __forceinline__ uint32_t to_tf32(float x) {
    uint32_t u;
    asm("cvt.rna.tf32.f32 %0, %1;" : "=r"(u) : "f"(x));
    return u;
}

__device__ __forceinline__ void mma_tf32(float* c,
                                         uint32_t a0, uint32_t a1, uint32_t a2, uint32_t a3,
                                         uint32_t b0, uint32_t b1) {
    asm volatile(
        "mma.sync.aligned.m16n8k8.row.col.f32.tf32.tf32.f32 "
        "{%0,%1,%2,%3},{%4,%5,%6,%7},{%8,%9},{%0,%1,%2,%3};\n"
        : "+f"(c[0]), "+f"(c[1]), "+f"(c[2]), "+f"(c[3])
        : "r"(a0), "r"(a1), "r"(a2), "r"(a3), "r"(b0), "r"(b1));
}

// ---------------------------------------------------------------------------
// Smem fragment layouts per 128x64x16 chunk (same as R6):
//  A: float4 aSm[16][32], B: float2 bSm[2][64][4], XOR-swizzled.
// ---------------------------------------------------------------------------

__device__ __forceinline__ void ldgA(const float* __restrict__ g, int ld, int row0, int k0,
                                     int t, float4 st[4]) {
    int ks = t >> 6, mg = (t >> 3) & 7, r = t & 7;
    const float* p = g + (size_t)(row0 + mg * 16 + r) * ld + (k0 + ks * 8);
    st[0] = ld4(p); st[1] = ld4(p + 4);
    p += (size_t)8 * ld;
    st[2] = ld4(p); st[3] = ld4(p + 4);
}
__device__ __forceinline__ void stsA(float4* aSm, int t, const float4 st[4]) {
    int ks = t >> 6, mg = (t >> 3) & 7, r = t & 7;
    int base = (ks * 8 + mg) * 32, sw = (r >> 1) & 3, r4 = r * 4;
    aSm[base + ((r4 + 0) ^ sw)] = make_float4(st[0].x, st[2].x, st[1].x, st[3].x);
    aSm[base + ((r4 + 1) ^ sw)] = make_float4(st[0].y, st[2].y, st[1].y, st[3].y);
    aSm[base + ((r4 + 2) ^ sw)] = make_float4(st[0].z, st[2].z, st[1].z, st[3].z);
    aSm[base + ((r4 + 3) ^ sw)] = make_float4(st[0].w, st[2].w, st[1].w, st[3].w);
}

__device__ __forceinline__ void ldgBD(const float* __restrict__ g, int ld, int k0, int col0,
                                      int t, float4 st[2]) {
    int kq = t & 3, cg = (t >> 2) & 15, ks = t >> 6;
    const float* p = g + (size_t)(k0 + ks * 8 + kq) * ld + col0 + cg * 4;
    st[0] = ld4(p);
    st[1] = ld4(p + (size_t)4 * ld);
}
__device__ __forceinline__ void stsBD(float2* bSm, int t, const float4 st[2]) {
    int kq = t & 3, cg = (t >> 2) & 15, ks = t >> 6;
    int base = (ks * 64 + cg * 4) * 4 + (kq ^ (cg & 3));
    bSm[base + 0]  = make_float2(st[0].x, st[1].x);
    bSm[base + 4]  = make_float2(st[0].y, st[1].y);
    bSm[base + 8]  = make_float2(st[0].z, st[1].z);
    bSm[base + 12] = make_float2(st[0].w, st[1].w);
}

__device__ __forceinline__ void ldgBT(const float* __restrict__ g, int ld, int row0, int k0,
                                      int t, float4 st[2]) {
    int cc = t & 63, ks = t >> 6;
    const float* p = g + (size_t)(row0 + cc) * ld + k0 + ks * 8;
    st[0] = ld4(p);
    st[1] = ld4(p + 4);
}
__device__ __forceinline__ void stsBT(float2* bSm, int t, const float4 st[2]) {
    int cc = t & 63, ks = t >> 6;
    int sw = (cc >> 2) & 3;
    int base = (ks * 64 + cc) * 4;
    bSm[base + (0 ^ sw)] = make_float2(st[0].x, st[1].x);
    bSm[base + (1 ^ sw)] = make_float2(st[0].y, st[1].y);
    bSm[base + (2 ^ sw)] = make_float2(st[0].z, st[1].z);
    bSm[base + (3 ^ sw)] = make_float2(st[0].w, st[1].w);
}

// ---------------------------------------------------------------------------
// Compute one k16 chunk. Warp tile 64x32. 2xTF32 split: acc += Ah*Bh + Al*Bh.
// ---------------------------------------------------------------------------
__device__ __forceinline__ void computeChunk(const float4* __restrict__ aSm,
                                             const float2* __restrict__ bSm,
                                             int mBase, int nBase, int lane,
                                             float acc[4][4][4]) {
    const int sl  = lane ^ ((lane >> 3) & 3);
    const int kqc = lane & 3;
    const int cr  = lane >> 2;
    const int mg0 = mBase >> 4;
#pragma unroll
    for (int ks = 0; ks < 2; ++ks) {
        uint32_t ah[4][4], al[4][4];
#pragma unroll
        for (int mt = 0; mt < 4; ++mt) {
            float4 fa = aSm[(ks * 8 + mg0 + mt) * 32 + sl];
            splitu(fa.x, ah[mt][0], al[mt][0]);
            splitu(fa.y, ah[mt][1], al[mt][1]);
            splitu(fa.z, ah[mt][2], al[mt][2]);
            splitu(fa.w, ah[mt][3], al[mt][3]);
        }
#pragma unroll
        for (int nt = 0; nt < 4; ++nt) {
            int cc = nBase + nt * 8 + cr;
            float2 fb = bSm[(ks * 64 + cc) * 4 + (kqc ^ ((cc >> 2) & 3))];
            uint32_t bh0 = to_tf32(fb.x);
            uint32_t bh1 = to_tf32(fb.y);
#pragma unroll
            for (int mt = 0; mt < 4; ++mt) {
                mma_tf32(acc[mt][nt], ah[mt][0], ah[mt][1], ah[mt][2], ah[mt][3], bh0, bh1);
                mma_tf32(acc[mt][nt], al[mt][0], al[mt][1], al[mt][2], al[mt][3], bh0, bh1);
            }
        }
    }
}

// ---------------------------------------------------------------------------
// Double-buffered mainloop. BT: B source is [n][k].
// ---------------------------------------------------------------------------
template <bool BT>
__device__ __forceinline__ void gemm_mainloop(
    const float* __restrict__ Ag, int lda, int arow0,
    const float* __restrict__ Bg, int ldb, int b0,
    int nChunks, int tid, int mBase, int nBase, int lane,
    float4* aSm, float2* bSm, float acc[4][4][4])
{
    float4 stA[4], stB[2];
    ldgA(Ag, lda, arow0, 0, tid, stA);
    if (BT) ldgBT(Bg, ldb, b0, 0, tid, stB);
    else    ldgBD(Bg, ldb, 0, b0, tid, stB);
    stsA(aSm, tid, stA);
    if (BT) stsBT(bSm, tid, stB);
    else    stsBD(bSm, tid, stB);

    for (int c = 0; c < nChunks; ++c) {
        __syncthreads();
        const bool more = (c + 1) < nChunks;
        if (more) {
            const int k0 = (c + 1) * 16;
            ldgA(Ag, lda, arow0, k0, tid, stA);
            if (BT) ldgBT(Bg, ldb, b0, k0, tid, stB);
            else    ldgBD(Bg, ldb, k0, b0, tid, stB);
        }
        const int cb = c & 1;
        computeChunk(aSm + cb * 512, bSm + cb * 512, mBase, nBase, lane, acc);
        if (more) {
            const int nb = (c + 1) & 1;
            stsA(aSm + nb * 512, tid, stA);
            if (BT) stsBT(bSm + nb * 512, tid, stB);
            else    stsBD(bSm + nb * 512, tid, stB);
        }
    }
}

#define DECL_SMEM() \
    __shared__ float4 aSm[1024]; \
    __shared__ float2 bSm[1024]

#define INIT_ACC(acc) \
    _Pragma("unroll") for (int _a = 0; _a < 4; ++_a) \
    _Pragma("unroll") for (int _b = 0; _b < 4; ++_b) \
    _Pragma("unroll") for (int _d = 0; _d < 4; ++_d) acc[_a][_b][_d] = 0.f

// ---------------------------------------------------------------------------
// Kernel 1: projections + decay folding.
//   z=0: Qt = (xq@Wq) * s * gamma^(-i)
//   z=1: Kt = (xk@Wk) * s * gamma^(+j)
//   z=2: V  =  xv@Wv
// grid (128, 4, 3), block 128
// ---------------------------------------------------------------------------
__global__ __launch_bounds__(128, 3)
void proj_kernel(const float* __restrict__ xq, const float* __restrict__ xk,
                 const float* __restrict__ xv,
                 const float* __restrict__ Wq, const float* __restrict__ Wk,
                 const float* __restrict__ Wv,
                 float sScale, float log2gi) {
    DECL_SMEM();
    const int tid = threadIdx.x, lane = tid & 31, warp = tid >> 5;
    const int mBase = (warp >> 1) * 64, nBase = (warp & 1) * 32;
    const int row0 = blockIdx.x * 128, col0 = blockIdx.y * 64;
    const int z = blockIdx.z;

    const float* X; const float* W; float* O;
    if (z == 0)      { X = xq; W = Wq; O = g_Q; }
    else if (z == 1) { X = xk; W = Wk; O = g_K; }
    else             { X = xv; W = Wv; O = g_V; }

    float acc[4][4][4];
    INIT_ACC(acc);
    gemm_mainloop<false>(X, DIN, row0, W, DIMN, col0, DIN / 16,
                         tid, mBase, nBase, lane, aSm, bSm, acc);

#pragma unroll
    for (int mt = 0; mt < 4; ++mt) {
        const int r = row0 + mBase + mt * 16 + (lane >> 2);
        // sequence index within batch (rows are [b*2048 + s])
        float f0 = 1.f, f1 = 1.f;
        if (z == 0) {
            f0 = sScale * exp2f((float)(r & (SS - 1)) * log2gi);
            f1 = sScale * exp2f((float)((r + 8) & (SS - 1)) * log2gi);
        } else if (z == 1) {
            f0 = sScale * exp2f(-(float)(r & (SS - 1)) * log2gi);
            f1 = sScale * exp2f(-(float)((r + 8) & (SS - 1)) * log2gi);
        }
#pragma unroll
        for (int nt = 0; nt < 4; ++nt) {
            int cc = col0 + nBase + nt * 8 + (lane & 3) * 2;
            *reinterpret_cast<float2*>(O + (size_t)r * DIMN + cc) =
                make_float2(acc[mt][nt][0] * f0, acc[mt][nt][1] * f0);
            *reinterpret_cast<float2*>(O + (size_t)(r + 8) * DIMN + cc) =
                make_float2(acc[mt][nt][2] * f1, acc[mt][nt][3] * f1);
        }
    }
}

// ---------------------------------------------------------------------------
// Kernel 2: scores = tril(Qt Kt^T)  — pure masked GEMM now (no exp2f!).
// grid (272, 8): L = i2*(i2+1) + j, j in 0..2*i2+1.
// ---------------------------------------------------------------------------
__global__ __launch_bounds__(128, 3)
void scores_kernel() {
    DECL_SMEM();
    __shared__ float rowAcc[128];

    const int tid = threadIdx.x, lane = tid & 31, warp = tid >> 5;
    const int mBase = (warp >> 1) * 64, nBase = (warp & 1) * 32;
    const int L = blockIdx.x, b = blockIdx.y;

    int i2 = (int)((sqrtf(4.f * (float)L + 1.f) - 1.f) * 0.5f);
    while ((i2 + 1) * (i2 + 2) <= L) ++i2;
    while (i2 * (i2 + 1) > L) --i2;
    const int j = L - i2 * (i2 + 1);     // 0 <= j <= 2*i2+1

    const float* Qp = g_Q + (size_t)b * SS * DIMN;
    const float* Kp = g_K + (size_t)b * SS * DIMN;

    rowAcc[tid] = 0.f;

    float acc[4][4][4];
    INIT_ACC(acc);
    gemm_mainloop<true>(Qp, DIMN, i2 * 128, Kp, DIMN, j * 64, DIMN / 16,
                        tid, mBase, nBase, lane, aSm, bSm, acc);

    float* Sp = g_scores + (size_t)b * SS * SS;
#pragma unroll
    for (int mt = 0; mt < 4; ++mt)
#pragma unroll
        for (int h = 0; h < 2; ++h) {
            const int lr   = mBase + mt * 16 + h * 8 + (lane >> 2);
            const int grow = i2 * 128 + lr;
            float rsum = 0.f;
#pragma unroll
            for (int nt = 0; nt < 4; ++nt) {
                const int gcol = j * 64 + nBase + nt * 8 + (lane & 3) * 2;
                const int d0 = grow - gcol;
                const int d1 = d0 - 1;
                float v0 = (d0 >= 0) ? acc[mt][nt][h * 2 + 0] : 0.f;
                float v1 = (d1 >= 0) ? acc[mt][nt][h * 2 + 1] : 0.f;
                *reinterpret_cast<float2*>(Sp + (size_t)grow * SS + gcol) = make_float2(v0, v1);
                rsum += v0 + v1;
            }
            rsum += __shfl_xor_sync(0xffffffffu, rsum, 1);
            rsum += __shfl_xor_sync(0xffffffffu, rsum, 2);
            if ((lane & 3) == 0) atomicAdd(&rowAcc[lr], rsum);  // 2 commutative adds/slot
        }
    __syncthreads();
    g_part[((size_t)b * SS + i2 * 128 + tid) * 32 + j] = rowAcc[tid];
}

// ---------------------------------------------------------------------------
// Kernel 3: V[t,:] /= max(|rowsum_t|, 1)  (sequential, deterministic)
// ---------------------------------------------------------------------------
__global__ void vprime_kernel() {
    const int row = blockIdx.x;
    const int s   = row & (SS - 1);
    __shared__ float inv;
    if (threadIdx.x == 0) {
        float acc = 0.f;
        const int jm = s >> 6;
        const float* p = g_part + (size_t)row * 32;
        for (int jt = 0; jt <= jm; ++jt) acc += p[jt];
        inv = 1.f / fmaxf(fabsf(acc), 1.f);
    }
    __syncthreads();
    g_V[(size_t)row * DIMN + threadIdx.x] *= inv;
}

// ---------------------------------------------------------------------------
// Kernel 4: out = scores @ V'. Uniform-work pairing: block x handles row
// tiles i2 = x and 15 - x => every block does exactly 17*8 chunks.
// grid (8, 4, 8) = 256 identical blocks.
// ---------------------------------------------------------------------------
__global__ __launch_bounds__(128, 3)
void out_kernel(float* __restrict__ out) {
    DECL_SMEM();
    const int tid = threadIdx.x, lane = tid & 31, warp = tid >> 5;
    const int mBase = (warp >> 1) * 64, nBase = (warp & 1) * 32;
    const int col0 = blockIdx.y * 64;
    const int b = blockIdx.z;

    const float* Sp = g_scores + (size_t)b * SS * SS;
    const float* Vp = g_V + (size_t)b * SS * DIMN;
    float* Ob = out + (size_t)b * SS * DIMN;

#pragma unroll 1
    for (int half = 0; half < 2; ++half) {
        const int i2 = half ? (15 - (int)blockIdx.x) : (int)blockIdx.x;

        __syncthreads();   // protect smem reuse across the two mainloops

        float acc[4][4][4];
        INIT_ACC(acc);

        gemm_mainloop<false>(Sp, SS, i2 * 128, Vp, DIMN, col0, (i2 + 1) * 8,
                             tid, mBase, nBase, lane, aSm, bSm, acc);

#pragma unroll
        for (int mt = 0; mt < 4; ++mt)
#pragma unroll
            for (int nt = 0; nt < 4; ++nt) {
                int r  = i2 * 128 + mBase + mt * 16 + (lane >> 2);
                int cc = col0 + nBase + nt * 8 + (lane & 3) * 2;
                *reinterpret_cast<float2*>(Ob + (size_t)r * DIMN + cc) =
                    make_float2(acc[mt][nt][0], acc[mt][nt][1]);
                *reinterpret_cast<float2*>(Ob + (size_t)(r + 8) * DIMN + cc) =
                    make_float2(acc[mt][nt][2], acc[mt][nt][3]);
            }
    }
}

// ---------------------------------------------------------------------------
// Launch
// ---------------------------------------------------------------------------
extern "C" void kernel_launch(void* const* d_in, const int* in_sizes, int n_in,
                              void* d_out, int out_size) {
    const float* xq = (const float*)d_in[0];
    const float* xk = (const float*)d_in[1];
    const float* xv = (const float*)d_in[2];
    const float* Wq = (const float*)d_in[3];
    const float* Wk = (const float*)d_in[4];
    const float* Wv = (const float*)d_in[5];
    float* out = (float*)d_out;

    // sum|D| = sum_{d=0}^{S-1} (S-d) * gamma^(-d);  D[i,j] = gamma^(j-i), i>=j
    double acc = 0.0, gp = 1.0;
    const double ginv = 1.0 / GAMMA;
    for (int d = 0; d < SS; ++d) { acc += (double)(SS - d) * gp; gp *= ginv; }
    const double scoreScale = 1.0 / (sqrt(acc) * 16.0);   // invNorm / sqrt(dim)
    const float sScale = (float)sqrt(scoreScale);         // split between Qt and Kt
    const float log2gi = (float)(-log(GAMMA) / log(2.0)); // log2(1/gamma) > 0

    proj_kernel<<<dim3(128, 4, 3), 128>>>(xq, xk, xv, Wq, Wk, Wv, sScale, log2gi);
    scores_kernel<<<dim3(272, 8), 128>>>();
    vprime_kernel<<<BB * SS, 256>>>();
    out_kernel<<<dim3(8, 4, 8), 128>>>(out);
}